// round 11
// baseline (speedup 1.0000x reference)
#include <cuda_runtime.h>

// Problem constants
#define CCH     12            // path channels: 1 time + 3 orig + 8 aug
#define TT      1024
#define NCHUNK  16
#define CHLEN   64            // chunk 15 has 63 steps (16*64-1 = 1023)
#define NPATH   64            // B(32) * GROUPS(2)
#define NBATCH  32
#define SIGC    1884          // 12 + 144 + 1728
#define L2OFF   12
#define L3OFF   156
#define TSTRIDE 68            // padded t-stride of transposed dx (float4-aligned)
#define SIGQ    471           // SIGC / 4 float4s

// Shared pool sizing: phase 2 needs 4*SIGC floats (30.1 KB) per burst.
#define POOLF   (4 * SIGC)    // 7536 floats

// Scratch (no cudaMalloc allowed)
__device__ __align__(16) float g_part[NPATH * NCHUNK * SIGC]; // ~7.7 MB
__device__ __align__(16) float g_sig [NPATH * SIGC];          // ~0.5 MB
__device__ int g_path_cnt [NPATH];    // zero-init; self-resetting
__device__ int g_batch_cnt[NBATCH];   // zero-init; self-resetting

// ---------------------------------------------------------------------------
// Single fused kernel. grid = (NCHUNK, NPATH) = 1024 blocks, block = 160.
// Phase 1 (all blocks): partial signature of one 64-step chunk (FFMA2 path).
//   smem pool overlaid with dx buffers.
// Phase 2 (last block per path): fold 16 partials; 4 bursts of 4 partials
//   bulk-staged into the pool (coalesced), folds read smem only.
// Phase 3 (last path per batch): stage sig pair to pool, 32-output GEMV.
// ---------------------------------------------------------------------------
__global__ __launch_bounds__(160) void sig_fused_kernel(
        const float* __restrict__ x,
        const float* __restrict__ aug_w,
        const float* __restrict__ lin_w,
        const float* __restrict__ lin_b,
        float* __restrict__ out)
{
    __shared__ __align__(16) float pool[POOLF];   // 30.1 KB, reused per phase
    __shared__ int sh_last;

    // Phase-1 overlays inside the pool
    float* dxsh = pool;                               // CHLEN*CCH = 768
    float* dxT  = pool + 768;                         // CCH*TSTRIDE = 816
    float* xsh  = pool + 768 + 816;                   // (CHLEN+1)*3 = 195
    float* awsh = pool + 768 + 816 + 200;             // 24

    const int tid   = threadIdx.x;
    const int chunk = blockIdx.x;
    const int p     = blockIdx.y;        // path id = b*2 + g
    const int b     = p >> 1;
    const int g     = p & 1;
    const int t0    = chunk * CHLEN;
    const int ns    = (chunk == NCHUNK - 1) ? (CHLEN - 1) : CHLEN;   // steps

    // ------------------------- Phase 1: chunk partial -------------------------
    for (int idx = tid; idx < (ns + 1) * 3; idx += blockDim.x)
        xsh[idx] = x[(b * TT + t0) * 3 + idx];
    if (tid < 24) awsh[tid] = aug_w[g * 24 + tid];
    __syncthreads();

    for (int idx = tid; idx < ns * CCH; idx += blockDim.x) {
        int t = idx / CCH, c = idx - t * CCH;
        float xd0 = xsh[(t + 1) * 3 + 0] - xsh[t * 3 + 0];
        float xd1 = xsh[(t + 1) * 3 + 1] - xsh[t * 3 + 1];
        float xd2 = xsh[(t + 1) * 3 + 2] - xsh[t * 3 + 2];
        float v;
        if (c == 0)      v = 1.0f / 1023.0f;
        else if (c == 1) v = xd0;
        else if (c == 2) v = xd1;
        else if (c == 3) v = xd2;
        else {
            int e = c - 4;
            v = fmaf(awsh[e * 3 + 0], xd0,
                fmaf(awsh[e * 3 + 1], xd1,
                     awsh[e * 3 + 2] * xd2));
        }
        dxsh[idx] = v;
        dxT[c * TSTRIDE + t] = v;
    }
    __syncthreads();

    if (tid < 144) {
        const int i = tid / CCH, j = tid - CCH * (tid / CCH);
        unsigned long long S3p[6];
#pragma unroll
        for (int k = 0; k < 6; k++) S3p[k] = 0ULL;
        float S2 = 0.0f;
        float s1 = 0.0f;
        const unsigned long long* __restrict__ dx64 =
            (const unsigned long long*)dxsh;                 // 6 u64 per row
        const float4* __restrict__ diT = (const float4*)(dxT + i * TSTRIDE);
        const float4* __restrict__ djT = (const float4*)(dxT + j * TSTRIDE);

#define SIG_STEP(tq, di_, dj_) {                                              \
        const unsigned long long* dp = dx64 + (size_t)(tq) * 6;               \
        const ulonglong2 v0 = *(const ulonglong2*)(dp);                       \
        const ulonglong2 v1 = *(const ulonglong2*)(dp + 2);                   \
        const ulonglong2 v2 = *(const ulonglong2*)(dp + 4);                   \
        const float cc = fmaf(fmaf((di_), 1.0f/6.0f, 0.5f * s1), (dj_), S2);  \
        unsigned long long ccp;                                               \
        asm("mov.b64 %0, {%1, %1};" : "=l"(ccp) : "f"(cc));                   \
        asm("fma.rn.f32x2 %0, %1, %2, %0;" : "+l"(S3p[0]) : "l"(ccp), "l"(v0.x)); \
        asm("fma.rn.f32x2 %0, %1, %2, %0;" : "+l"(S3p[1]) : "l"(ccp), "l"(v0.y)); \
        asm("fma.rn.f32x2 %0, %1, %2, %0;" : "+l"(S3p[2]) : "l"(ccp), "l"(v1.x)); \
        asm("fma.rn.f32x2 %0, %1, %2, %0;" : "+l"(S3p[3]) : "l"(ccp), "l"(v1.y)); \
        asm("fma.rn.f32x2 %0, %1, %2, %0;" : "+l"(S3p[4]) : "l"(ccp), "l"(v2.x)); \
        asm("fma.rn.f32x2 %0, %1, %2, %0;" : "+l"(S3p[5]) : "l"(ccp), "l"(v2.y)); \
        S2 = fmaf(fmaf((di_), 0.5f, s1), (dj_), S2);                          \
        s1 += (di_); }

        const int nq = ns >> 2;           // full quads of steps
#pragma unroll 4
        for (int tb = 0; tb < nq; tb++) {
            const float4 di4 = diT[tb];
            const float4 dj4 = djT[tb];
            SIG_STEP(tb * 4 + 0, di4.x, dj4.x);
            SIG_STEP(tb * 4 + 1, di4.y, dj4.y);
            SIG_STEP(tb * 4 + 2, di4.z, dj4.z);
            SIG_STEP(tb * 4 + 3, di4.w, dj4.w);
        }
        for (int t = nq * 4; t < ns; t++) {   // remainder (0 or 3 steps)
            const float di = dxT[i * TSTRIDE + t];
            const float dj = dxT[j * TSTRIDE + t];
            SIG_STEP(t, di, dj);
        }
#undef SIG_STEP

        float* o = &g_part[(size_t)(p * NCHUNK + chunk) * SIGC];
        if (j == 0) o[i] = s1;
        o[L2OFF + tid] = S2;
        ulonglong2* o2 = (ulonglong2*)(o + L3OFF + tid * 12);
        o2[0] = make_ulonglong2(S3p[0], S3p[1]);
        o2[1] = make_ulonglong2(S3p[2], S3p[3]);
        o2[2] = make_ulonglong2(S3p[4], S3p[5]);
    }

    // --------------------- Phase 2 gate: last block of path --------------------
    __threadfence();                 // release g_part writes
    __syncthreads();
    if (tid == 0) {
        int old = atomicAdd(&g_path_cnt[p], 1);
        sh_last = (old == NCHUNK - 1);
        if (sh_last) g_path_cnt[p] = 0;     // reset for next replay
    }
    __syncthreads();
    if (!sh_last) return;

    // ------------- Phase 2: staged Chen-fold, 4 bursts of 4 partials -----------
    {
        const float* __restrict__ base = &g_part[(size_t)p * NCHUNK * SIGC];
        const int i    = (tid < 144) ? tid / CCH : 0;
        const int j    = (tid < 144) ? tid - CCH * i : 0;

        float A3[12];
        float A2ij = 0.f, a1i = 0.f;

        for (int w = 0; w < 4; w++) {
            __syncthreads();     // previous burst's reads done / pool free
            const float4* __restrict__ gp4 =
                (const float4*)(base + (size_t)w * 4 * SIGC);
            for (int f = tid; f < 4 * SIGQ; f += 160)
                ((float4*)pool)[f] = gp4[f];
            __syncthreads();

            if (tid < 144) {
                int s0 = 0;
                if (w == 0) {
                    // init from partial 0
                    const float4* p4 = (const float4*)(pool + L3OFF + tid * 12);
                    float4 v0 = p4[0], v1 = p4[1], v2 = p4[2];
                    A3[0] = v0.x; A3[1] = v0.y; A3[2]  = v0.z; A3[3]  = v0.w;
                    A3[4] = v1.x; A3[5] = v1.y; A3[6]  = v1.z; A3[7]  = v1.w;
                    A3[8] = v2.x; A3[9] = v2.y; A3[10] = v2.z; A3[11] = v2.w;
                    A2ij = pool[L2OFF + tid];
                    a1i  = pool[i];
                    s0 = 1;
                }
#pragma unroll 4
                for (int s = s0; s < 4; s++) {
                    const float* __restrict__ bp = pool + (size_t)s * SIGC;
                    const float4 u0 = *(const float4*)(bp + 0);
                    const float4 u1 = *(const float4*)(bp + 4);
                    const float4 u2 = *(const float4*)(bp + 8);
                    const float4 q0 = *(const float4*)(bp + L2OFF + j * 12 + 0);
                    const float4 q1 = *(const float4*)(bp + L2OFF + j * 12 + 4);
                    const float4 q2 = *(const float4*)(bp + L2OFF + j * 12 + 8);
                    const float4 r0 = *(const float4*)(bp + L3OFF + tid * 12 + 0);
                    const float4 r1 = *(const float4*)(bp + L3OFF + tid * 12 + 4);
                    const float4 r2 = *(const float4*)(bp + L3OFF + tid * 12 + 8);
                    const float  b2 = bp[L2OFF + i * CCH + j];
                    const float b1i = bp[i];
                    const float b1j = bp[j];

                    A3[0]  += r0.x + fmaf(a1i, q0.x, A2ij * u0.x);
                    A3[1]  += r0.y + fmaf(a1i, q0.y, A2ij * u0.y);
                    A3[2]  += r0.z + fmaf(a1i, q0.z, A2ij * u0.z);
                    A3[3]  += r0.w + fmaf(a1i, q0.w, A2ij * u0.w);
                    A3[4]  += r1.x + fmaf(a1i, q1.x, A2ij * u1.x);
                    A3[5]  += r1.y + fmaf(a1i, q1.y, A2ij * u1.y);
                    A3[6]  += r1.z + fmaf(a1i, q1.z, A2ij * u1.z);
                    A3[7]  += r1.w + fmaf(a1i, q1.w, A2ij * u1.w);
                    A3[8]  += r2.x + fmaf(a1i, q2.x, A2ij * u2.x);
                    A3[9]  += r2.y + fmaf(a1i, q2.y, A2ij * u2.y);
                    A3[10] += r2.z + fmaf(a1i, q2.z, A2ij * u2.z);
                    A3[11] += r2.w + fmaf(a1i, q2.w, A2ij * u2.w);
                    A2ij += b2 + a1i * b1j;
                    a1i  += b1i;
                }
            }
        }

        if (tid < 144) {
            float* so = &g_sig[(size_t)p * SIGC];
            if (j == 0) so[i] = a1i;
            so[L2OFF + tid] = A2ij;
            float4* o4 = (float4*)(so + L3OFF + tid * 12);
            o4[0] = make_float4(A3[0], A3[1], A3[2],  A3[3]);
            o4[1] = make_float4(A3[4], A3[5], A3[6],  A3[7]);
            o4[2] = make_float4(A3[8], A3[9], A3[10], A3[11]);
        }
    }

    // --------------------- Phase 3 gate: last path of batch --------------------
    __threadfence();                 // release g_sig writes
    __syncthreads();
    if (tid == 0) {
        int old = atomicAdd(&g_batch_cnt[b], 1);
        sh_last = (old == 1);
        if (sh_last) g_batch_cnt[b] = 0;    // reset for next replay
    }
    __syncthreads();
    if (!sh_last) return;

    // --------------------- Phase 3: GEMV + sigmoid for batch b -----------------
    {
        // Stage the batch's contiguous sig pair (15 KB) into the pool.
        const float4* __restrict__ gsig =
            (const float4*)&g_sig[(size_t)(2 * b) * SIGC];
        const int NV = (2 * SIGC) / 4;      // 942
        for (int f = tid; f < NV; f += 160)
            ((float4*)pool)[f] = gsig[f];
        __syncthreads();

        const int warp = tid >> 5;          // 0..4
        const int lane = tid & 31;
        const float4* __restrict__ s4 = (const float4*)pool;

        for (int o = warp; o < 32; o += 5) {
            const float4* __restrict__ w4 =
                (const float4*)(lin_w + (size_t)o * 2 * SIGC);
            float ax = 0.0f, ay = 0.0f, az = 0.0f, aw = 0.0f;
            for (int f = lane; f < NV; f += 32) {
                float4 sv = s4[f];
                float4 wv = w4[f];
                ax = fmaf(sv.x, wv.x, ax);
                ay = fmaf(sv.y, wv.y, ay);
                az = fmaf(sv.z, wv.z, az);
                aw = fmaf(sv.w, wv.w, aw);
            }
            float acc = (ax + ay) + (az + aw);
#pragma unroll
            for (int off = 16; off > 0; off >>= 1)
                acc += __shfl_down_sync(0xffffffffu, acc, off);
            if (lane == 0) {
                float z = acc + lin_b[o];
                out[b * 32 + o] = 1.0f / (1.0f + expf(-z));
            }
        }
    }
}

// ---------------------------------------------------------------------------
extern "C" void kernel_launch(void* const* d_in, const int* in_sizes, int n_in,
                              void* d_out, int out_size)
{
    const float* x     = (const float*)d_in[0];  // (32,1024,3)
    const float* aug_w = (const float*)d_in[1];  // (2,8,3)
    // d_in[2] = aug_b : unused (signature is translation-invariant)
    const float* lin_w = (const float*)d_in[3];  // (32, 3768)
    const float* lin_b = (const float*)d_in[4];  // (32,)
    float* out = (float*)d_out;                  // (32,32) float32

    dim3 grid(NCHUNK, NPATH);
    sig_fused_kernel<<<grid, 160>>>(x, aug_w, lin_w, lin_b, out);
}

// round 12
// speedup vs baseline: 2.0646x; 2.0646x over previous
#include <cuda_runtime.h>

// Problem constants
#define CCH     12            // path channels: 1 time + 3 orig + 8 aug
#define TT      1024
#define NCHTOT  12            // chunks per path
#define WPB     6             // chunk-workers per block
#define CHLEN   86            // 11*86 + 77 = 1023 steps
#define NPATH   64            // B(32) * GROUPS(2)
#define NBATCH  32
#define SIGC    1884          // 12 + 144 + 1728
#define L2OFF   12
#define L3OFF   156
#define TSTRIDE 88            // padded t-stride of transposed dx (16B-aligned rows)
#define SIGQ    471           // SIGC / 4 float4s
#define WSTRIDE 2376          // per-worker phase-1 smem floats (16B multiple)

// Scratch (no cudaMalloc allowed): 2 half-path partials per path
__device__ __align__(16) float g_part2[NPATH * 2 * SIGC];   // ~965 KB (L2-resident)

// ---------------------------------------------------------------------------
// Kernel 1: grid = (2, NPATH) = 128 blocks, block = 864 (27 full warps, zero
// dead lanes; SMSP issue split 7/7/7/6).
// Phase A: worker w (144 threads) computes the partial signature of chunk
//          h*6+w (<=86 steps) with FFMA2-packed S3.
// Phase B: store partials to smem, fold 6 -> 1 in-block, write g_part2.
// ---------------------------------------------------------------------------
extern __shared__ float pool[];   // union: phase A 6*WSTRIDE | phase B 6*SIGC

__global__ __launch_bounds__(864, 1) void half_path_kernel(
        const float* __restrict__ x,
        const float* __restrict__ aug_w)
{
    const int tid = threadIdx.x;
    const int h   = blockIdx.x;          // half: chunks h*6 .. h*6+5
    const int p   = blockIdx.y;          // path id = b*2 + g
    const int b   = p >> 1;
    const int g   = p & 1;

    const int w   = tid / 144;           // worker 0..5
    const int r   = tid - 144 * w;       // 0..143
    const int chunk = h * WPB + w;
    const int t0    = chunk * CHLEN;
    const int ns    = (chunk == NCHTOT - 1) ? (1023 - t0) : CHLEN;  // 86 or 77

    float* base = pool + w * WSTRIDE;
    float* dxsh = base;                  // [t][c]  86*12 = 1032
    float* dxT  = base + 1032;           // [c][t]  12*88 = 1056
    float* xsh  = base + 2088;           // 261 (+3 pad)
    float* awsh = base + 2352;           // 24

    // ---- Phase A: stage x + weights, build dx (both layouts) ----
    for (int idx = r; idx < (ns + 1) * 3; idx += 144)
        xsh[idx] = x[(b * TT + t0) * 3 + idx];
    if (r < 24) awsh[r] = aug_w[g * 24 + r];
    __syncthreads();

    for (int idx = r; idx < ns * CCH; idx += 144) {
        int t = idx / CCH, c = idx - t * CCH;
        float xd0 = xsh[(t + 1) * 3 + 0] - xsh[t * 3 + 0];
        float xd1 = xsh[(t + 1) * 3 + 1] - xsh[t * 3 + 1];
        float xd2 = xsh[(t + 1) * 3 + 2] - xsh[t * 3 + 2];
        float v;
        if (c == 0)      v = 1.0f / 1023.0f;
        else if (c == 1) v = xd0;
        else if (c == 2) v = xd1;
        else if (c == 3) v = xd2;
        else {
            int e = c - 4;
            v = fmaf(awsh[e * 3 + 0], xd0,
                fmaf(awsh[e * 3 + 1], xd1,
                     awsh[e * 3 + 2] * xd2));
        }
        dxsh[idx] = v;
        dxT[c * TSTRIDE + t] = v;
    }
    __syncthreads();

    // ---- Phase A: 86-step scan, thread (i,j) of worker w ----
    const int i = r / CCH, j = r - CCH * (r / CCH);
    unsigned long long S3p[6];
#pragma unroll
    for (int k = 0; k < 6; k++) S3p[k] = 0ULL;
    float S2 = 0.0f;
    float s1 = 0.0f;
    {
        const unsigned long long* __restrict__ dx64 =
            (const unsigned long long*)dxsh;                 // 6 u64 per row
        const float4* __restrict__ diT = (const float4*)(dxT + i * TSTRIDE);
        const float4* __restrict__ djT = (const float4*)(dxT + j * TSTRIDE);

#define SIG_STEP(tq, di_, dj_) {                                              \
        const unsigned long long* dp = dx64 + (size_t)(tq) * 6;               \
        const ulonglong2 v0 = *(const ulonglong2*)(dp);                       \
        const ulonglong2 v1 = *(const ulonglong2*)(dp + 2);                   \
        const ulonglong2 v2 = *(const ulonglong2*)(dp + 4);                   \
        const float cc = fmaf(fmaf((di_), 1.0f/6.0f, 0.5f * s1), (dj_), S2);  \
        unsigned long long ccp;                                               \
        asm("mov.b64 %0, {%1, %1};" : "=l"(ccp) : "f"(cc));                   \
        asm("fma.rn.f32x2 %0, %1, %2, %0;" : "+l"(S3p[0]) : "l"(ccp), "l"(v0.x)); \
        asm("fma.rn.f32x2 %0, %1, %2, %0;" : "+l"(S3p[1]) : "l"(ccp), "l"(v0.y)); \
        asm("fma.rn.f32x2 %0, %1, %2, %0;" : "+l"(S3p[2]) : "l"(ccp), "l"(v1.x)); \
        asm("fma.rn.f32x2 %0, %1, %2, %0;" : "+l"(S3p[3]) : "l"(ccp), "l"(v1.y)); \
        asm("fma.rn.f32x2 %0, %1, %2, %0;" : "+l"(S3p[4]) : "l"(ccp), "l"(v2.x)); \
        asm("fma.rn.f32x2 %0, %1, %2, %0;" : "+l"(S3p[5]) : "l"(ccp), "l"(v2.y)); \
        S2 = fmaf(fmaf((di_), 0.5f, s1), (dj_), S2);                          \
        s1 += (di_); }

        const int nq = ns >> 2;
#pragma unroll 4
        for (int tb = 0; tb < nq; tb++) {
            const float4 di4 = diT[tb];
            const float4 dj4 = djT[tb];
            SIG_STEP(tb * 4 + 0, di4.x, dj4.x);
            SIG_STEP(tb * 4 + 1, di4.y, dj4.y);
            SIG_STEP(tb * 4 + 2, di4.z, dj4.z);
            SIG_STEP(tb * 4 + 3, di4.w, dj4.w);
        }
        for (int t = nq * 4; t < ns; t++) {   // remainder (1 or 2 steps)
            const float di = dxT[i * TSTRIDE + t];
            const float dj = dxT[j * TSTRIDE + t];
            SIG_STEP(t, di, dj);
        }
#undef SIG_STEP
    }

    // ---- Phase B: partials -> smem (overlays phase-A buffers; all compute
    //      results are in registers), then in-block 6 -> 1 fold ----
    __syncthreads();   // everyone done reading dx buffers
    {
        float* o = pool + w * SIGC;
        if (j == 0) o[i] = s1;
        o[L2OFF + r] = S2;
        ulonglong2* o2 = (ulonglong2*)(o + L3OFF + r * 12);
        o2[0] = make_ulonglong2(S3p[0], S3p[1]);
        o2[1] = make_ulonglong2(S3p[2], S3p[3]);
        o2[2] = make_ulonglong2(S3p[4], S3p[5]);
    }
    __syncthreads();

    if (tid < 432) {
        const int t144 = tid / 3;
        const int kg   = tid - 3 * t144;
        const int fi   = t144 / CCH;
        const int fj   = t144 - CCH * fi;

        float4 A3   = *(const float4*)(pool + L3OFF + t144 * 12 + kg * 4);
        float  A2ij = pool[L2OFF + t144];
        float  a1i  = pool[fi];

#pragma unroll
        for (int s = 1; s < WPB; s++) {
            const float* __restrict__ bp = pool + s * SIGC;
            const float4 u4  = *(const float4*)(bp + kg * 4);
            const float  b1i = bp[fi];
            const float  b1j = bp[fj];
            const float4 q   = *(const float4*)(bp + L2OFF + fj * 12 + kg * 4);
            const float  b2  = bp[L2OFF + fi * CCH + fj];
            const float4 rr  = *(const float4*)(bp + L3OFF + t144 * 12 + kg * 4);

            A3.x += rr.x; A3.x = fmaf(a1i, q.x, A3.x); A3.x = fmaf(A2ij, u4.x, A3.x);
            A3.y += rr.y; A3.y = fmaf(a1i, q.y, A3.y); A3.y = fmaf(A2ij, u4.y, A3.y);
            A3.z += rr.z; A3.z = fmaf(a1i, q.z, A3.z); A3.z = fmaf(A2ij, u4.z, A3.z);
            A3.w += rr.w; A3.w = fmaf(a1i, q.w, A3.w); A3.w = fmaf(A2ij, u4.w, A3.w);
            A2ij += b2 + a1i * b1j;
            a1i  += b1i;
        }

        float* out = &g_part2[(size_t)(p * 2 + h) * SIGC];
        *(float4*)(out + L3OFF + t144 * 12 + kg * 4) = A3;
        if (kg == 0) {
            out[L2OFF + t144] = A2ij;
            if (fj == 0) out[fi] = a1i;
        }
    }
}

// ---------------------------------------------------------------------------
// Kernel 2: final fold + GEMV + sigmoid. grid = 32 (batch), block = 1024.
// Stage the batch's 4 half-partials (30 KB), one Chen fold per path,
// write sig into the A slots, then 32-warp GEMV from smem.
// ---------------------------------------------------------------------------
__global__ __launch_bounds__(1024) void finish_kernel(
        const float* __restrict__ lin_w,
        const float* __restrict__ lin_b,
        float* __restrict__ out)
{
    __shared__ __align__(16) float sp[4 * SIGC];   // 30.1 KB

    const int tid = threadIdx.x;
    const int b   = blockIdx.x;

    // Stage: paths 2b, 2b+1 -> 4 contiguous SIGC partials
    const float4* __restrict__ gsrc = (const float4*)&g_part2[(size_t)4 * b * SIGC];
    for (int f = tid; f < 4 * SIGQ; f += 1024)
        ((float4*)sp)[f] = gsrc[f];
    __syncthreads();

    float4 A3 = make_float4(0.f, 0.f, 0.f, 0.f);
    float  A2ij = 0.f, a1i = 0.f;
    int ph = 0, t144 = 0, kg = 0, fi = 0, fj = 0;
    if (tid < 864) {
        ph   = tid / 432;                 // path-in-batch
        const int u = tid - 432 * ph;
        t144 = u / 3;
        kg   = u - 3 * t144;
        fi   = t144 / CCH;
        fj   = t144 - CCH * fi;

        const float* A = sp + (size_t)ph * 2 * SIGC;       // first half
        A3   = *(const float4*)(A + L3OFF + t144 * 12 + kg * 4);
        A2ij = A[L2OFF + t144];
        a1i  = A[fi];
    }
    __syncthreads();   // all init reads of A slots done before overwrite

    if (tid < 864) {
        const float* __restrict__ bp = sp + ((size_t)ph * 2 + 1) * SIGC;  // second half
        const float4 u4  = *(const float4*)(bp + kg * 4);
        const float  b1i = bp[fi];
        const float  b1j = bp[fj];
        const float4 q   = *(const float4*)(bp + L2OFF + fj * 12 + kg * 4);
        const float  b2  = bp[L2OFF + fi * CCH + fj];
        const float4 rr  = *(const float4*)(bp + L3OFF + t144 * 12 + kg * 4);

        A3.x += rr.x; A3.x = fmaf(a1i, q.x, A3.x); A3.x = fmaf(A2ij, u4.x, A3.x);
        A3.y += rr.y; A3.y = fmaf(a1i, q.y, A3.y); A3.y = fmaf(A2ij, u4.y, A3.y);
        A3.z += rr.z; A3.z = fmaf(a1i, q.z, A3.z); A3.z = fmaf(A2ij, u4.z, A3.z);
        A3.w += rr.w; A3.w = fmaf(a1i, q.w, A3.w); A3.w = fmaf(A2ij, u4.w, A3.w);
        A2ij += b2 + a1i * b1j;
        a1i  += b1i;

        // write final sig into the A slot
        float* so = sp + (size_t)ph * 2 * SIGC;
        *(float4*)(so + L3OFF + t144 * 12 + kg * 4) = A3;
        if (kg == 0) {
            so[L2OFF + t144] = A2ij;
            if (fj == 0) so[fi] = a1i;
        }
    }
    __syncthreads();

    // GEMV + sigmoid: warp o -> out[b][o]
    const int o    = tid >> 5;
    const int lane = tid & 31;
    const float4* __restrict__ s0 = (const float4*)sp;                       // path 2b
    const float4* __restrict__ s1 = (const float4*)(sp + 2 * SIGC);          // path 2b+1
    const float4* __restrict__ w4 = (const float4*)(lin_w + (size_t)o * 2 * SIGC);

    float ax = 0.0f, ay = 0.0f, az = 0.0f, aw = 0.0f;
    for (int f = lane; f < SIGQ; f += 32) {
        float4 sv = s0[f];
        float4 wv = w4[f];
        ax = fmaf(sv.x, wv.x, ax);
        ay = fmaf(sv.y, wv.y, ay);
        az = fmaf(sv.z, wv.z, az);
        aw = fmaf(sv.w, wv.w, aw);
    }
    for (int f = lane; f < SIGQ; f += 32) {
        float4 sv = s1[f];
        float4 wv = w4[SIGQ + f];
        ax = fmaf(sv.x, wv.x, ax);
        ay = fmaf(sv.y, wv.y, ay);
        az = fmaf(sv.z, wv.z, az);
        aw = fmaf(sv.w, wv.w, aw);
    }
    float acc = (ax + ay) + (az + aw);
#pragma unroll
    for (int off = 16; off > 0; off >>= 1)
        acc += __shfl_down_sync(0xffffffffu, acc, off);
    if (lane == 0) {
        float z = acc + lin_b[o];
        out[b * 32 + o] = 1.0f / (1.0f + expf(-z));
    }
}

// ---------------------------------------------------------------------------
extern "C" void kernel_launch(void* const* d_in, const int* in_sizes, int n_in,
                              void* d_out, int out_size)
{
    const float* x     = (const float*)d_in[0];  // (32,1024,3)
    const float* aug_w = (const float*)d_in[1];  // (2,8,3)
    // d_in[2] = aug_b : unused (signature is translation-invariant)
    const float* lin_w = (const float*)d_in[3];  // (32, 3768)
    const float* lin_b = (const float*)d_in[4];  // (32,)
    float* out = (float*)d_out;                  // (32,32) float32

    // dyn smem: max(phase A 6*WSTRIDE, phase B 6*SIGC) floats
    const int dynA = WPB * WSTRIDE;              // 14256
    const int dynB = WPB * SIGC;                 // 11304
    const int dyn_smem = (dynA > dynB ? dynA : dynB) * (int)sizeof(float);  // 57 KB
    cudaFuncSetAttribute(half_path_kernel,
                         cudaFuncAttributeMaxDynamicSharedMemorySize, dyn_smem);

    dim3 grid1(2, NPATH);
    half_path_kernel<<<grid1, 864, dyn_smem>>>(x, aug_w);
    finish_kernel<<<NBATCH, 1024>>>(lin_w, lin_b, out);
}

// round 13
// speedup vs baseline: 2.2121x; 1.0714x over previous
#include <cuda_runtime.h>

// Problem constants
#define CCH     12            // path channels: 1 time + 3 orig + 8 aug
#define TT      1024
#define NCHTOT  12            // chunks per path
#define WPB     6             // chunk-workers per block
#define CHLEN   86            // 11*86 + 77 = 1023 steps
#define NPATH   64            // B(32) * GROUPS(2)
#define NBATCH  32
#define SIGC    1884          // 12 + 144 + 1728
#define L2OFF   12
#define L3OFF   156
#define TSTRIDE 88            // padded t-stride of transposed dx (16B-aligned rows)
#define SIGQ    471           // SIGC / 4 float4s
#define WSTRIDE 2376          // per-worker phase-1 smem floats (16B multiple)

// Scratch (no cudaMalloc allowed)
__device__ __align__(16) float g_part2[NPATH * 2 * SIGC];   // ~965 KB (L2-resident)
__device__ __align__(16) float g_acc[NBATCH * 32 * 2];      // partial dots per (b,o,g)
__device__ int g_cnt[NBATCH];                               // zero-init; self-resetting

// ---------------------------------------------------------------------------
// Kernel 1 (unchanged R12 winner): grid = (2, NPATH) = 128 blocks, block = 864
// (27 full warps, zero dead lanes). Worker w (144 thr) scans chunk h*6+w with
// FFMA2-packed S3; then in-block 6 -> 1 Chen fold; write half-partial.
// ---------------------------------------------------------------------------
extern __shared__ float pool[];   // union: phase A 6*WSTRIDE | phase B 6*SIGC

__global__ __launch_bounds__(864, 1) void half_path_kernel(
        const float* __restrict__ x,
        const float* __restrict__ aug_w)
{
    const int tid = threadIdx.x;
    const int h   = blockIdx.x;          // half: chunks h*6 .. h*6+5
    const int p   = blockIdx.y;          // path id = b*2 + g
    const int b   = p >> 1;
    const int g   = p & 1;

    const int w   = tid / 144;           // worker 0..5
    const int r   = tid - 144 * w;       // 0..143
    const int chunk = h * WPB + w;
    const int t0    = chunk * CHLEN;
    const int ns    = (chunk == NCHTOT - 1) ? (1023 - t0) : CHLEN;  // 86 or 77

    float* base = pool + w * WSTRIDE;
    float* dxsh = base;                  // [t][c]  86*12 = 1032
    float* dxT  = base + 1032;           // [c][t]  12*88 = 1056
    float* xsh  = base + 2088;           // 261 (+3 pad)
    float* awsh = base + 2352;           // 24

    // ---- Phase A: stage x + weights, build dx (both layouts) ----
    for (int idx = r; idx < (ns + 1) * 3; idx += 144)
        xsh[idx] = x[(b * TT + t0) * 3 + idx];
    if (r < 24) awsh[r] = aug_w[g * 24 + r];
    __syncthreads();

    for (int idx = r; idx < ns * CCH; idx += 144) {
        int t = idx / CCH, c = idx - t * CCH;
        float xd0 = xsh[(t + 1) * 3 + 0] - xsh[t * 3 + 0];
        float xd1 = xsh[(t + 1) * 3 + 1] - xsh[t * 3 + 1];
        float xd2 = xsh[(t + 1) * 3 + 2] - xsh[t * 3 + 2];
        float v;
        if (c == 0)      v = 1.0f / 1023.0f;
        else if (c == 1) v = xd0;
        else if (c == 2) v = xd1;
        else if (c == 3) v = xd2;
        else {
            int e = c - 4;
            v = fmaf(awsh[e * 3 + 0], xd0,
                fmaf(awsh[e * 3 + 1], xd1,
                     awsh[e * 3 + 2] * xd2));
        }
        dxsh[idx] = v;
        dxT[c * TSTRIDE + t] = v;
    }
    __syncthreads();

    // ---- Phase A: scan, thread (i,j) of worker w ----
    const int i = r / CCH, j = r - CCH * (r / CCH);
    unsigned long long S3p[6];
#pragma unroll
    for (int k = 0; k < 6; k++) S3p[k] = 0ULL;
    float S2 = 0.0f;
    float s1 = 0.0f;
    {
        const unsigned long long* __restrict__ dx64 =
            (const unsigned long long*)dxsh;                 // 6 u64 per row
        const float4* __restrict__ diT = (const float4*)(dxT + i * TSTRIDE);
        const float4* __restrict__ djT = (const float4*)(dxT + j * TSTRIDE);

#define SIG_STEP(tq, di_, dj_) {                                              \
        const unsigned long long* dp = dx64 + (size_t)(tq) * 6;               \
        const ulonglong2 v0 = *(const ulonglong2*)(dp);                       \
        const ulonglong2 v1 = *(const ulonglong2*)(dp + 2);                   \
        const ulonglong2 v2 = *(const ulonglong2*)(dp + 4);                   \
        const float cc = fmaf(fmaf((di_), 1.0f/6.0f, 0.5f * s1), (dj_), S2);  \
        unsigned long long ccp;                                               \
        asm("mov.b64 %0, {%1, %1};" : "=l"(ccp) : "f"(cc));                   \
        asm("fma.rn.f32x2 %0, %1, %2, %0;" : "+l"(S3p[0]) : "l"(ccp), "l"(v0.x)); \
        asm("fma.rn.f32x2 %0, %1, %2, %0;" : "+l"(S3p[1]) : "l"(ccp), "l"(v0.y)); \
        asm("fma.rn.f32x2 %0, %1, %2, %0;" : "+l"(S3p[2]) : "l"(ccp), "l"(v1.x)); \
        asm("fma.rn.f32x2 %0, %1, %2, %0;" : "+l"(S3p[3]) : "l"(ccp), "l"(v1.y)); \
        asm("fma.rn.f32x2 %0, %1, %2, %0;" : "+l"(S3p[4]) : "l"(ccp), "l"(v2.x)); \
        asm("fma.rn.f32x2 %0, %1, %2, %0;" : "+l"(S3p[5]) : "l"(ccp), "l"(v2.y)); \
        S2 = fmaf(fmaf((di_), 0.5f, s1), (dj_), S2);                          \
        s1 += (di_); }

        const int nq = ns >> 2;
#pragma unroll 4
        for (int tb = 0; tb < nq; tb++) {
            const float4 di4 = diT[tb];
            const float4 dj4 = djT[tb];
            SIG_STEP(tb * 4 + 0, di4.x, dj4.x);
            SIG_STEP(tb * 4 + 1, di4.y, dj4.y);
            SIG_STEP(tb * 4 + 2, di4.z, dj4.z);
            SIG_STEP(tb * 4 + 3, di4.w, dj4.w);
        }
        for (int t = nq * 4; t < ns; t++) {   // remainder (1 or 2 steps)
            const float di = dxT[i * TSTRIDE + t];
            const float dj = dxT[j * TSTRIDE + t];
            SIG_STEP(t, di, dj);
        }
#undef SIG_STEP
    }

    // ---- Phase B: partials -> smem, then in-block 6 -> 1 fold ----
    __syncthreads();   // everyone done reading dx buffers
    {
        float* o = pool + w * SIGC;
        if (j == 0) o[i] = s1;
        o[L2OFF + r] = S2;
        ulonglong2* o2 = (ulonglong2*)(o + L3OFF + r * 12);
        o2[0] = make_ulonglong2(S3p[0], S3p[1]);
        o2[1] = make_ulonglong2(S3p[2], S3p[3]);
        o2[2] = make_ulonglong2(S3p[4], S3p[5]);
    }
    __syncthreads();

    if (tid < 432) {
        const int t144 = tid / 3;
        const int kg   = tid - 3 * t144;
        const int fi   = t144 / CCH;
        const int fj   = t144 - CCH * fi;

        float4 A3   = *(const float4*)(pool + L3OFF + t144 * 12 + kg * 4);
        float  A2ij = pool[L2OFF + t144];
        float  a1i  = pool[fi];

#pragma unroll
        for (int s = 1; s < WPB; s++) {
            const float* __restrict__ bp = pool + s * SIGC;
            const float4 u4  = *(const float4*)(bp + kg * 4);
            const float  b1i = bp[fi];
            const float  b1j = bp[fj];
            const float4 q   = *(const float4*)(bp + L2OFF + fj * 12 + kg * 4);
            const float  b2  = bp[L2OFF + fi * CCH + fj];
            const float4 rr  = *(const float4*)(bp + L3OFF + t144 * 12 + kg * 4);

            A3.x += rr.x; A3.x = fmaf(a1i, q.x, A3.x); A3.x = fmaf(A2ij, u4.x, A3.x);
            A3.y += rr.y; A3.y = fmaf(a1i, q.y, A3.y); A3.y = fmaf(A2ij, u4.y, A3.y);
            A3.z += rr.z; A3.z = fmaf(a1i, q.z, A3.z); A3.z = fmaf(A2ij, u4.z, A3.z);
            A3.w += rr.w; A3.w = fmaf(a1i, q.w, A3.w); A3.w = fmaf(A2ij, u4.w, A3.w);
            A2ij += b2 + a1i * b1j;
            a1i  += b1i;
        }

        float* out = &g_part2[(size_t)(p * 2 + h) * SIGC];
        *(float4*)(out + L3OFF + t144 * 12 + kg * 4) = A3;
        if (kg == 0) {
            out[L2OFF + t144] = A2ij;
            if (fj == 0) out[fi] = a1i;
        }
    }
}

// ---------------------------------------------------------------------------
// Kernel 2: per-path fold + partial GEMV; last path of batch does
// sum + bias + sigmoid. grid = NPATH (64 blocks), block = 1024.
// Stage this path's two half-partials (15 KB), one Chen fold, then 32 warps
// compute partial dots of this path's SIGC segment vs each lin_w row half.
// Partial dots land in per-(b,o,g) slots -> deterministic (no float atomics).
// ---------------------------------------------------------------------------
__global__ __launch_bounds__(1024) void finish_kernel(
        const float* __restrict__ lin_w,
        const float* __restrict__ lin_b,
        float* __restrict__ out)
{
    __shared__ __align__(16) float sp[2 * SIGC];   // 15 KB
    __shared__ int sh_last;

    const int tid = threadIdx.x;
    const int p   = blockIdx.x;          // path = b*2 + g
    const int b   = p >> 1;
    const int g   = p & 1;

    // Stage both half-partials of this path
    const float4* __restrict__ gsrc = (const float4*)&g_part2[(size_t)2 * p * SIGC];
    for (int f = tid; f < 2 * SIGQ; f += 1024)
        ((float4*)sp)[f] = gsrc[f];
    __syncthreads();

    // Fold half1 into half0 (432 threads), result sig in sp[0..SIGC)
    if (tid < 432) {
        const int t144 = tid / 3;
        const int kg   = tid - 3 * t144;
        const int fi   = t144 / CCH;
        const int fj   = t144 - CCH * fi;

        float4 A3   = *(const float4*)(sp + L3OFF + t144 * 12 + kg * 4);
        float  A2ij = sp[L2OFF + t144];
        float  a1i  = sp[fi];

        const float* __restrict__ bp = sp + SIGC;
        const float4 u4  = *(const float4*)(bp + kg * 4);
        const float  b1i = bp[fi];
        const float  b1j = bp[fj];
        const float4 q   = *(const float4*)(bp + L2OFF + fj * 12 + kg * 4);
        const float  b2  = bp[L2OFF + fi * CCH + fj];
        const float4 rr  = *(const float4*)(bp + L3OFF + t144 * 12 + kg * 4);

        A3.x += rr.x; A3.x = fmaf(a1i, q.x, A3.x); A3.x = fmaf(A2ij, u4.x, A3.x);
        A3.y += rr.y; A3.y = fmaf(a1i, q.y, A3.y); A3.y = fmaf(A2ij, u4.y, A3.y);
        A3.z += rr.z; A3.z = fmaf(a1i, q.z, A3.z); A3.z = fmaf(A2ij, u4.z, A3.z);
        A3.w += rr.w; A3.w = fmaf(a1i, q.w, A3.w); A3.w = fmaf(A2ij, u4.w, A3.w);
        A2ij += b2 + a1i * b1j;
        a1i  += b1i;

        *(float4*)(sp + L3OFF + t144 * 12 + kg * 4) = A3;
        if (kg == 0) {
            sp[L2OFF + t144] = A2ij;
            if (fj == 0) sp[fi] = a1i;
        }
    }
    __syncthreads();

    // Partial GEMV: warp o computes dot(sig_p, lin_w[o][g*SIGC ..]) (471 quads)
    {
        const int o    = tid >> 5;
        const int lane = tid & 31;
        const float4* __restrict__ s4 = (const float4*)sp;
        const float4* __restrict__ w4 =
            (const float4*)(lin_w + (size_t)o * 2 * SIGC + (size_t)g * SIGC);

        float ax = 0.0f, ay = 0.0f, az = 0.0f, aw = 0.0f;
        for (int f = lane; f < SIGQ; f += 32) {
            float4 sv = s4[f];
            float4 wv = w4[f];
            ax = fmaf(sv.x, wv.x, ax);
            ay = fmaf(sv.y, wv.y, ay);
            az = fmaf(sv.z, wv.z, az);
            aw = fmaf(sv.w, wv.w, aw);
        }
        float acc = (ax + ay) + (az + aw);
#pragma unroll
        for (int off = 16; off > 0; off >>= 1)
            acc += __shfl_down_sync(0xffffffffu, acc, off);
        if (lane == 0)
            g_acc[(b * 32 + o) * 2 + g] = acc;
    }

    // Gate: last path of batch applies bias + sigmoid
    __threadfence();
    __syncthreads();
    if (tid == 0) {
        int old = atomicAdd(&g_cnt[b], 1);
        sh_last = (old == 1);
        if (sh_last) g_cnt[b] = 0;      // reset for next replay
    }
    __syncthreads();
    if (!sh_last) return;
    __threadfence();                    // acquire other path's g_acc writes

    if (tid < 32) {
        float z = g_acc[(b * 32 + tid) * 2 + 0]
                + g_acc[(b * 32 + tid) * 2 + 1]
                + lin_b[tid];
        out[b * 32 + tid] = 1.0f / (1.0f + expf(-z));
    }
}

// ---------------------------------------------------------------------------
extern "C" void kernel_launch(void* const* d_in, const int* in_sizes, int n_in,
                              void* d_out, int out_size)
{
    const float* x     = (const float*)d_in[0];  // (32,1024,3)
    const float* aug_w = (const float*)d_in[1];  // (2,8,3)
    // d_in[2] = aug_b : unused (signature is translation-invariant)
    const float* lin_w = (const float*)d_in[3];  // (32, 3768)
    const float* lin_b = (const float*)d_in[4];  // (32,)
    float* out = (float*)d_out;                  // (32,32) float32

    // dyn smem: max(phase A 6*WSTRIDE, phase B 6*SIGC) floats
    const int dynA = WPB * WSTRIDE;              // 14256
    const int dynB = WPB * SIGC;                 // 11304
    const int dyn_smem = (dynA > dynB ? dynA : dynB) * (int)sizeof(float);  // 57 KB
    cudaFuncSetAttribute(half_path_kernel,
                         cudaFuncAttributeMaxDynamicSharedMemorySize, dyn_smem);

    dim3 grid1(2, NPATH);
    half_path_kernel<<<grid1, 864, dyn_smem>>>(x, aug_w);
    finish_kernel<<<NPATH, 1024>>>(lin_w, lin_b, out);
}